// round 1
// baseline (speedup 1.0000x reference)
#include <cuda_runtime.h>

// Problem constants
#define NODES 4096
#define KTOT  16384          // NODES * N_REL : flattened contraction dim (m,b)
#define NC    128            // DOUT * N_REL  : flattened output cols (e,a)

// GEMM tiling
#define BM 128
#define BN 128
#define BK 32
#define SPLITS 16
#define KCH (KTOT / SPLITS)  // 1024

// Scratch (no cudaMalloc allowed -> __device__ globals)
__device__ float g_V[KTOT * NC];                       // 8 MB  : V[q, c]
__device__ float g_part[SPLITS * NODES * NC];          // 32 MB : split-K partials

// ---------------------------------------------------------------------------
// V[m*4+b, e*4+a] = sum_d x[m,d,(a-b)&3] * W[d,e,b]
// x: (4096, 32, 4) contiguous ; W: (32, 32, 4) contiguous
// ---------------------------------------------------------------------------
__global__ __launch_bounds__(128) void prep_kernel(const float* __restrict__ x,
                                                   const float* __restrict__ w) {
    __shared__ float xs[128];    // x[m, :, :]
    __shared__ float ws[4096];   // full W
    const int m = blockIdx.x;
    const int t = threadIdx.x;   // t = e*4 + a
    xs[t] = x[m * 128 + t];
#pragma unroll
    for (int i = 0; i < 32; i++) ws[i * 128 + t] = w[i * 128 + t];
    __syncthreads();

    const int a = t & 3, e = t >> 2;
    float acc[4] = {0.f, 0.f, 0.f, 0.f};
#pragma unroll
    for (int d = 0; d < 32; d++) {
#pragma unroll
        for (int b = 0; b < 4; b++) {
            const int j = (a - b) & 3;
            acc[b] += xs[d * 4 + j] * ws[d * 128 + e * 4 + b];
        }
    }
#pragma unroll
    for (int b = 0; b < 4; b++)
        g_V[(m * 4 + b) * NC + t] = acc[b];
}

// ---------------------------------------------------------------------------
// C_partial[split] (128x128 tile) += A(4096x16384) @ V(16384x128) over K chunk.
// fp32, packed fma.rn.f32x2 (pairs along N) to reach the full-rate FP32 path.
// ---------------------------------------------------------------------------
__global__ __launch_bounds__(256) void gemm_kernel(const float* __restrict__ A) {
    __shared__ float As[BK][BM + 4];
    __shared__ float Vs[BK][BN + 4];

    const int m0 = blockIdx.x * BM;
    const int k0 = blockIdx.y * KCH;
    const int tid = threadIdx.x;
    const int tx = tid & 15, ty = tid >> 4;   // 16x16 thread grid, 8x8 per thread

    unsigned long long acc2[8][4];            // 8 M-rows x 4 f32x2 (8 N-cols)
#pragma unroll
    for (int i = 0; i < 8; i++)
#pragma unroll
        for (int j = 0; j < 4; j++) acc2[i][j] = 0ULL;

    for (int kk = 0; kk < KCH; kk += BK) {
        // A tile: 128 rows x 32 k, vectorized, stored transposed As[k][m]
#pragma unroll
        for (int p = 0; p < 4; p++) {
            const int idx = tid + p * 256;
            const int row = idx >> 3, c4 = idx & 7;
            const float4 va = *(const float4*)(A + (size_t)(m0 + row) * KTOT +
                                               (k0 + kk + c4 * 4));
            As[c4 * 4 + 0][row] = va.x;
            As[c4 * 4 + 1][row] = va.y;
            As[c4 * 4 + 2][row] = va.z;
            As[c4 * 4 + 3][row] = va.w;
        }
        // V tile: 32 k x 128 cols, row-major vectorized
#pragma unroll
        for (int p = 0; p < 4; p++) {
            const int idx = tid + p * 256;
            const int row = idx >> 5, c4 = idx & 31;
            *(float4*)&Vs[row][c4 * 4] =
                *(const float4*)(g_V + (k0 + kk + row) * NC + c4 * 4);
        }
        __syncthreads();

#pragma unroll
        for (int k = 0; k < BK; k++) {
            float af[8];
            *(float4*)&af[0] = *(float4*)&As[k][ty * 8];
            *(float4*)&af[4] = *(float4*)&As[k][ty * 8 + 4];
            unsigned long long v2[4];
            *(float4*)&v2[0] = *(float4*)&Vs[k][tx * 8];
            *(float4*)&v2[2] = *(float4*)&Vs[k][tx * 8 + 4];
#pragma unroll
            for (int i = 0; i < 8; i++) {
                unsigned long long a2;
                const unsigned int ab = __float_as_uint(af[i]);
                asm("mov.b64 %0, {%1, %1};" : "=l"(a2) : "r"(ab));
#pragma unroll
                for (int j = 0; j < 4; j++)
                    asm("fma.rn.f32x2 %0, %1, %2, %0;"
                        : "+l"(acc2[i][j]) : "l"(a2), "l"(v2[j]));
            }
        }
        __syncthreads();
    }

    float* outp = g_part + (size_t)blockIdx.y * (NODES * NC);
#pragma unroll
    for (int i = 0; i < 8; i++) {
        const int m = m0 + ty * 8 + i;
#pragma unroll
        for (int j = 0; j < 4; j++) {
            float lo, hi;
            asm("mov.b64 {%0, %1}, %2;" : "=f"(lo), "=f"(hi) : "l"(acc2[i][j]));
            const int n = tx * 8 + 2 * j;
            *(float2*)&outp[m * NC + n] = make_float2(lo, hi);
        }
    }
}

// ---------------------------------------------------------------------------
// Deterministic split-K reduction
// ---------------------------------------------------------------------------
__global__ __launch_bounds__(256) void reduce_kernel(float* __restrict__ out) {
    const int i = blockIdx.x * 256 + threadIdx.x;   // 0 .. 524287
    float s = 0.f;
#pragma unroll
    for (int p = 0; p < SPLITS; p++)
        s += g_part[(size_t)p * (NODES * NC) + i];
    out[i] = s;
}

// ---------------------------------------------------------------------------
extern "C" void kernel_launch(void* const* d_in, const int* in_sizes, int n_in,
                              void* d_out, int out_size) {
    const float* x   = (const float*)d_in[0];   // (4096, 32, 4)
    const float* adj = (const float*)d_in[1];   // (4096, 4096, 4) == A (4096 x 16384)
    const float* w   = (const float*)d_in[2];   // (32, 32, 4)
    float* out = (float*)d_out;                 // (4096, 32, 4)
    (void)in_sizes; (void)n_in; (void)out_size;

    prep_kernel<<<NODES, 128>>>(x, w);
    gemm_kernel<<<dim3(NODES / BM, SPLITS), 256>>>(adj);
    reduce_kernel<<<(NODES * NC) / 256, 256>>>(out);
}

// round 3
// speedup vs baseline: 2.7255x; 2.7255x over previous
#include <cuda_runtime.h>
#include <cstdint>

// ---------------------------------------------------------------------------
// out[n, e*4+a] = sum_{m,b} adj[n, m*4+b] * Vk[m*4+b, e*4+a]
//   Vk[q=m*4+b, c=e*4+a] = sum_d x[m,d,(a-b)&3] * W[d,e,b]
// One GEMM: C[4096,128] = A[4096,16384] @ Vk[16384,128], A = adj contiguous.
// Legacy tensor-core path: mma.sync.m16n8k8.tf32 (sm_80 feature -> compiles
// at compute_100; tcgen05 is unavailable because harness PTX targets sm_100).
// ---------------------------------------------------------------------------
#define NODES 4096
#define KTOT  16384
#define NC    128

#define BM 128
#define BN 128
#define BK 32
#define SPLITS 8
#define KCH   (KTOT / SPLITS)   // 2048
#define ITERS (KCH / BK)        // 64
#define STAGES 3

#define ASTRIDE 36              // floats per A smem row (bank-conflict-free)
#define BSTRIDE 136             // floats per B smem row (bank-conflict-free)
#define AS_STAGE (BM * ASTRIDE) // 4608 floats
#define BS_STAGE (BK * BSTRIDE) // 4352 floats
#define SMEM_FLOATS (STAGES * (AS_STAGE + BS_STAGE))
#define SMEM_BYTES  (SMEM_FLOATS * 4)   // 107520

// truncation-bias correction: A operand (all-positive) is truncated to tf32
// by the tensor core; E[trunc loss] = 2^-11*ln2 relative -> 1/(1-that).
#define CORR 1.0003381f

__device__ __align__(128) float g_Vk[KTOT * NC];        // 8 MB  B operand [k][n]
__device__ float g_part[SPLITS * NODES * NC];           // 16 MB split-K partials

// ------------------------------ helpers ------------------------------------
__device__ __forceinline__ uint32_t smem_u32(const void* p) {
    uint32_t a;
    asm("{ .reg .u64 t; cvta.to.shared.u64 t, %1; cvt.u32.u64 %0, t; }"
        : "=r"(a) : "l"(p));
    return a;
}

__device__ __forceinline__ void cp_async16(uint32_t dst, const void* src) {
    asm volatile("cp.async.cg.shared.global [%0], [%1], 16;"
                 :: "r"(dst), "l"(src) : "memory");
}
__device__ __forceinline__ void cp_commit() {
    asm volatile("cp.async.commit_group;" ::: "memory");
}
template <int N>
__device__ __forceinline__ void cp_wait() {
    asm volatile("cp.async.wait_group %0;" :: "n"(N) : "memory");
}

__device__ __forceinline__ void mma_tf32(float* d, const uint32_t* a,
                                         const uint32_t* b) {
    asm volatile(
        "mma.sync.aligned.m16n8k8.row.col.f32.tf32.tf32.f32 "
        "{%0,%1,%2,%3}, {%4,%5,%6,%7}, {%8,%9}, {%0,%1,%2,%3};"
        : "+f"(d[0]), "+f"(d[1]), "+f"(d[2]), "+f"(d[3])
        : "r"(a[0]), "r"(a[1]), "r"(a[2]), "r"(a[3]), "r"(b[0]), "r"(b[1]));
}

// ---------------------------------------------------------------------------
// prep: Vk[(m*4+b)][c=e*4+a] = sum_d x[m,d,(a-b)&3] * W[d,e,b], RNA-rounded tf32
// ---------------------------------------------------------------------------
__global__ __launch_bounds__(128) void prep_kernel(const float* __restrict__ x,
                                                   const float* __restrict__ w) {
    __shared__ float ws[4096];
    __shared__ float xs[128];
    const int t = threadIdx.x;
#pragma unroll
    for (int i = 0; i < 32; i++) ws[i * 128 + t] = w[i * 128 + t];
    const int a = t & 3, e = t >> 2;

    for (int mm = 0; mm < 32; mm++) {
        const int m = blockIdx.x * 32 + mm;
        __syncthreads();
        xs[t] = x[m * 128 + t];
        __syncthreads();
        float acc[4] = {0.f, 0.f, 0.f, 0.f};
#pragma unroll
        for (int d = 0; d < 32; d++)
#pragma unroll
            for (int b = 0; b < 4; b++)
                acc[b] += xs[d * 4 + ((a - b) & 3)] * ws[d * 128 + e * 4 + b];
#pragma unroll
        for (int b = 0; b < 4; b++) {
            uint32_t r;
            asm("cvt.rna.tf32.f32 %0, %1;" : "=r"(r) : "f"(acc[b]));
            g_Vk[(size_t)(m * 4 + b) * NC + t] = __uint_as_float(r);
        }
    }
}

// ---------------------------------------------------------------------------
// GEMM: grid (32 m-tiles, 8 splits), 256 threads, 8 warps (4m x 2n),
// warp tile 32(m) x 64(n), mma m16n8k8 tf32.
// ---------------------------------------------------------------------------
__global__ __launch_bounds__(256, 2) void gemm_kernel(const float* __restrict__ A) {
    extern __shared__ float smem[];
    float* As = smem;                       // [STAGES][BM][ASTRIDE]
    float* Bs = smem + STAGES * AS_STAGE;   // [STAGES][BK][BSTRIDE]
    const uint32_t asb = smem_u32(As);
    const uint32_t bsb = smem_u32(Bs);

    const int tid = threadIdx.x;
    const int lane = tid & 31;
    const int wid = tid >> 5;
    const int wm = (wid & 3) * 32;          // warp m offset
    const int wn = (wid >> 2) * 64;         // warp n offset
    const int g = lane >> 2;                // groupID (0..7)
    const int c = lane & 3;                 // threadID in group (0..3)

    const int m0 = blockIdx.x * BM;
    const int k0 = blockIdx.y * KCH;

    // precomputed per-thread load indices
    const int a_row = tid >> 3, a_c4 = (tid & 7) * 4;        // +128 rows per rep
    const int b_row = tid >> 5, b_c4 = (tid & 31) * 4;       // +8 rows per rep

    float acc[2][8][4];
#pragma unroll
    for (int mi = 0; mi < 2; mi++)
#pragma unroll
        for (int ni = 0; ni < 8; ni++)
#pragma unroll
            for (int j = 0; j < 4; j++) acc[mi][ni][j] = 0.f;

    auto load_stage = [&](int slot, int it) {
        const int ko = k0 + it * BK;
        const uint32_t ad = asb + (uint32_t)(slot * AS_STAGE) * 4;
        const uint32_t bd = bsb + (uint32_t)(slot * BS_STAGE) * 4;
        // A tile: 128 rows x 32 floats (128B/row) = 1024 x 16B
#pragma unroll
        for (int p = 0; p < 4; p++) {
            const int row = a_row + p * 32;
            cp_async16(ad + (uint32_t)(row * ASTRIDE + a_c4) * 4,
                       A + (size_t)(m0 + row) * KTOT + ko + a_c4);
        }
        // B tile: 32 rows x 128 floats (512B/row) = 1024 x 16B
#pragma unroll
        for (int p = 0; p < 4; p++) {
            const int row = b_row + p * 8;
            cp_async16(bd + (uint32_t)(row * BSTRIDE + b_c4) * 4,
                       g_Vk + (size_t)(ko + row) * NC + b_c4);
        }
    };

    // prologue
#pragma unroll
    for (int s = 0; s < STAGES - 1; s++) { load_stage(s, s); cp_commit(); }

    for (int it = 0; it < ITERS; it++) {
        cp_wait<STAGES - 2>();
        __syncthreads();

        const int nld = it + STAGES - 1;
        if (nld < ITERS) load_stage(nld % STAGES, nld);
        cp_commit();

        const float* As_ = As + (it % STAGES) * AS_STAGE;
        const float* Bs_ = Bs + (it % STAGES) * BS_STAGE;
#pragma unroll
        for (int ks = 0; ks < 4; ks++) {
            const int kb = ks * 8;
            uint32_t af[2][4];
#pragma unroll
            for (int mi = 0; mi < 2; mi++) {
                const int r0 = wm + mi * 16 + g;
                af[mi][0] = __float_as_uint(As_[(r0)     * ASTRIDE + kb + c]);
                af[mi][1] = __float_as_uint(As_[(r0 + 8) * ASTRIDE + kb + c]);
                af[mi][2] = __float_as_uint(As_[(r0)     * ASTRIDE + kb + c + 4]);
                af[mi][3] = __float_as_uint(As_[(r0 + 8) * ASTRIDE + kb + c + 4]);
            }
            uint32_t bf[8][2];
#pragma unroll
            for (int ni = 0; ni < 8; ni++) {
                const int col = wn + ni * 8 + g;
                bf[ni][0] = __float_as_uint(Bs_[(kb + c)     * BSTRIDE + col]);
                bf[ni][1] = __float_as_uint(Bs_[(kb + c + 4) * BSTRIDE + col]);
            }
#pragma unroll
            for (int mi = 0; mi < 2; mi++)
#pragma unroll
                for (int ni = 0; ni < 8; ni++)
                    mma_tf32(acc[mi][ni], af[mi], bf[ni]);
        }
        __syncthreads();
    }

    // epilogue -> split-K partials
    float* outp = g_part + (size_t)blockIdx.y * (NODES * NC);
#pragma unroll
    for (int mi = 0; mi < 2; mi++) {
        const int row = m0 + wm + mi * 16 + g;
#pragma unroll
        for (int ni = 0; ni < 8; ni++) {
            const int col = wn + ni * 8 + 2 * c;
            *(float2*)&outp[(size_t)row * NC + col] =
                make_float2(acc[mi][ni][0], acc[mi][ni][1]);
            *(float2*)&outp[(size_t)(row + 8) * NC + col] =
                make_float2(acc[mi][ni][2], acc[mi][ni][3]);
        }
    }
}

// ---------------------------------------------------------------------------
__global__ __launch_bounds__(256) void reduce_kernel(float* __restrict__ out) {
    const int i = blockIdx.x * 256 + threadIdx.x;
    float s = 0.f;
#pragma unroll
    for (int p = 0; p < SPLITS; p++)
        s += g_part[(size_t)p * (NODES * NC) + i];
    out[i] = s * CORR;
}

// ---------------------------------------------------------------------------
extern "C" void kernel_launch(void* const* d_in, const int* in_sizes, int n_in,
                              void* d_out, int out_size) {
    const float* x   = (const float*)d_in[0];   // (4096, 32, 4)
    const float* adj = (const float*)d_in[1];   // (4096, 4096, 4)
    const float* w   = (const float*)d_in[2];   // (32, 32, 4)
    float* out = (float*)d_out;                 // (4096, 32, 4)
    (void)in_sizes; (void)n_in; (void)out_size;

    cudaFuncSetAttribute(gemm_kernel,
                         cudaFuncAttributeMaxDynamicSharedMemorySize, SMEM_BYTES);

    prep_kernel<<<128, 128>>>(x, w);
    gemm_kernel<<<dim3(NODES / BM, SPLITS), 256, SMEM_BYTES>>>(adj);
    reduce_kernel<<<(NODES * NC) / 256, 256>>>(out);
}

// round 4
// speedup vs baseline: 3.2712x; 1.2002x over previous
#include <cuda_runtime.h>
#include <cstdint>

// ---------------------------------------------------------------------------
// out[n, e*4+a] = sum_{m,b} adj[n, m*4+b] * Vk[m*4+b, e*4+a]
//   Vk[q=m*4+b, c=e*4+a] = sum_d x[m,d,(a-b)&3] * W[d,e,b]
// C[4096,128] = A[4096,16384] @ Vk ; A = adj (contiguous view).
// Tensor path: legacy mma.sync.m16n8k8.tf32 (tcgen05 unavailable: harness
// compiles PTX at plain sm_100).
// ---------------------------------------------------------------------------
#define NODES 4096
#define KTOT  16384
#define NC    128

#define BM 128
#define BK 32
#define SPLITS 8
#define KCH   (KTOT / SPLITS)   // 2048
#define ITERS (KCH / BK)        // 64
#define STAGES 3

#define ASTRIDE 36
#define AS_STAGE (BM * ASTRIDE)     // 4608 floats
#define BS_STAGE (BK * NC)          // 4096 floats (flat, fragment-packed)
#define SMEM_FLOATS (STAGES * (AS_STAGE + BS_STAGE))
#define SMEM_BYTES  (SMEM_FLOATS * 4)   // 104448

// tf32 truncation-bias correction for the all-positive A operand
#define CORR 1.0003381f

// B operand, fragment-packed: value B[k][col] stored at
//   g_Vp[(k>>3)*1024 + col*8 + 2*((k&7)&3) + ((k&7)>>2)]
__device__ __align__(128) float g_Vp[KTOT * NC];        // 8 MB
__device__ float g_part[SPLITS * NODES * NC];           // 16 MB

// ------------------------------ helpers ------------------------------------
__device__ __forceinline__ uint32_t smem_u32(const void* p) {
    uint32_t a;
    asm("{ .reg .u64 t; cvta.to.shared.u64 t, %1; cvt.u32.u64 %0, t; }"
        : "=r"(a) : "l"(p));
    return a;
}
__device__ __forceinline__ void cp_async16(uint32_t dst, const void* src) {
    asm volatile("cp.async.cg.shared.global [%0], [%1], 16;"
                 :: "r"(dst), "l"(src) : "memory");
}
__device__ __forceinline__ void cp_commit() {
    asm volatile("cp.async.commit_group;" ::: "memory");
}
template <int N>
__device__ __forceinline__ void cp_wait() {
    asm volatile("cp.async.wait_group %0;" :: "n"(N) : "memory");
}
__device__ __forceinline__ void mma_tf32(float* d, const uint32_t* a,
                                         const uint32_t* b) {
    asm volatile(
        "mma.sync.aligned.m16n8k8.row.col.f32.tf32.tf32.f32 "
        "{%0,%1,%2,%3}, {%4,%5,%6,%7}, {%8,%9}, {%0,%1,%2,%3};"
        : "+f"(d[0]), "+f"(d[1]), "+f"(d[2]), "+f"(d[3])
        : "r"(a[0]), "r"(a[1]), "r"(a[2]), "r"(a[3]), "r"(b[0]), "r"(b[1]));
}

// ---------------------------------------------------------------------------
// prep: 512 blocks x 128 thr, 8 nodes per block. Writes fragment-packed g_Vp.
// ---------------------------------------------------------------------------
__global__ __launch_bounds__(128) void prep_kernel(const float* __restrict__ x,
                                                   const float* __restrict__ w) {
    __shared__ float ws[4096];
    __shared__ float xs[128];
    const int t = threadIdx.x;
#pragma unroll
    for (int i = 0; i < 32; i++) ws[i * 128 + t] = w[i * 128 + t];
    const int a = t & 3, e = t >> 2;

#pragma unroll
    for (int mm = 0; mm < 8; mm++) {
        const int m = blockIdx.x * 8 + mm;
        __syncthreads();
        xs[t] = x[m * 128 + t];
        __syncthreads();
        float acc[4] = {0.f, 0.f, 0.f, 0.f};
#pragma unroll
        for (int d = 0; d < 32; d++)
#pragma unroll
            for (int b = 0; b < 4; b++)
                acc[b] += xs[d * 4 + ((a - b) & 3)] * ws[d * 128 + e * 4 + b];
        // q = 4m+b -> slab = m>>1, j = 4(m&1)+b -> pos = col*8 + 2b + (m&1)
        float* dst = g_Vp + (size_t)(m >> 1) * 1024 + t * 8 + (m & 1);
#pragma unroll
        for (int b = 0; b < 4; b++) {
            uint32_t r;
            asm("cvt.rna.tf32.f32 %0, %1;" : "=r"(r) : "f"(acc[b]));
            dst[2 * b] = __uint_as_float(r);
        }
    }
}

// ---------------------------------------------------------------------------
// GEMM: grid (32 m-tiles, 8 splits), 128 threads = 4 warps (2m x 2n),
// warp tile 64x64 (mi=4, ni=8), mma m16n8k8 tf32.
// ---------------------------------------------------------------------------
__global__ __launch_bounds__(128, 2) void gemm_kernel(const float* __restrict__ A) {
    extern __shared__ float smem[];
    float* As = smem;                       // [STAGES][128][ASTRIDE]
    float* Bs = smem + STAGES * AS_STAGE;   // [STAGES][4 slabs][128 cols][8]
    const uint32_t asb = smem_u32(As);
    const uint32_t bsb = smem_u32(Bs);

    const int tid = threadIdx.x;
    const int lane = tid & 31;
    const int wid = tid >> 5;
    const int wm = (wid & 1) * 64;
    const int wn = (wid >> 1) * 64;
    const int g = lane >> 2;
    const int c = lane & 3;

    const int m0 = blockIdx.x * BM;
    const int k0 = blockIdx.y * KCH;
    const int slab0 = k0 >> 3;

    const int a_row = tid >> 3, a_c4 = (tid & 7) * 4;

    float acc[4][8][4];
#pragma unroll
    for (int mi = 0; mi < 4; mi++)
#pragma unroll
        for (int ni = 0; ni < 8; ni++)
#pragma unroll
            for (int j = 0; j < 4; j++) acc[mi][ni][j] = 0.f;

    auto load_stage = [&](int slot, int it) {
        const int ko = k0 + it * BK;
        const uint32_t ad = asb + (uint32_t)(slot * AS_STAGE) * 4;
        const uint32_t bd = bsb + (uint32_t)(slot * BS_STAGE) * 4;
        // A: 128 rows x 32 floats = 1024 x 16B chunks
#pragma unroll
        for (int p = 0; p < 8; p++) {
            const int row = a_row + p * 16;
            cp_async16(ad + (uint32_t)(row * ASTRIDE + a_c4) * 4,
                       A + (size_t)(m0 + row) * KTOT + ko + a_c4);
        }
        // B: flat 16KB slab copy (4 k-slabs, fragment-packed in gmem)
        const float* srcB = g_Vp + (size_t)(slab0 + it * 4) * 1024;
#pragma unroll
        for (int p = 0; p < 8; p++) {
            const int idx = tid + p * 128;
            cp_async16(bd + (uint32_t)idx * 16, srcB + idx * 4);
        }
    };

#pragma unroll
    for (int s = 0; s < STAGES - 1; s++) { load_stage(s, s); cp_commit(); }

    for (int it = 0; it < ITERS; it++) {
        cp_wait<STAGES - 2>();
        __syncthreads();

        const int nld = it + STAGES - 1;
        if (nld < ITERS) load_stage(nld % STAGES, nld);
        cp_commit();

        const float* As_ = As + (it % STAGES) * AS_STAGE;
        const float* Bs_ = Bs + (it % STAGES) * BS_STAGE;
#pragma unroll
        for (int ks = 0; ks < 4; ks++) {
            const int kb = ks * 8;
            uint32_t af[4][4];
#pragma unroll
            for (int mi = 0; mi < 4; mi++) {
                const int r0 = wm + mi * 16 + g;
                af[mi][0] = __float_as_uint(As_[(r0)     * ASTRIDE + kb + c]);
                af[mi][1] = __float_as_uint(As_[(r0 + 8) * ASTRIDE + kb + c]);
                af[mi][2] = __float_as_uint(As_[(r0)     * ASTRIDE + kb + c + 4]);
                af[mi][3] = __float_as_uint(As_[(r0 + 8) * ASTRIDE + kb + c + 4]);
            }
            uint32_t bf[8][2];
#pragma unroll
            for (int ni = 0; ni < 8; ni++) {
                const int col = wn + ni * 8 + g;
                const float2 v = *(const float2*)&Bs_[ks * 1024 + col * 8 + 2 * c];
                bf[ni][0] = __float_as_uint(v.x);
                bf[ni][1] = __float_as_uint(v.y);
            }
#pragma unroll
            for (int mi = 0; mi < 4; mi++)
#pragma unroll
                for (int ni = 0; ni < 8; ni++)
                    mma_tf32(acc[mi][ni], af[mi], bf[ni]);
        }
        __syncthreads();
    }

    float* outp = g_part + (size_t)blockIdx.y * (NODES * NC);
#pragma unroll
    for (int mi = 0; mi < 4; mi++) {
        const int row = m0 + wm + mi * 16 + g;
#pragma unroll
        for (int ni = 0; ni < 8; ni++) {
            const int col = wn + ni * 8 + 2 * c;
            *(float2*)&outp[(size_t)row * NC + col] =
                make_float2(acc[mi][ni][0], acc[mi][ni][1]);
            *(float2*)&outp[(size_t)(row + 8) * NC + col] =
                make_float2(acc[mi][ni][2], acc[mi][ni][3]);
        }
    }
}

// ---------------------------------------------------------------------------
__global__ __launch_bounds__(256) void reduce_kernel(float* __restrict__ out) {
    const int i4 = (blockIdx.x * 256 + threadIdx.x) * 4;
    float4 s = make_float4(0.f, 0.f, 0.f, 0.f);
#pragma unroll
    for (int p = 0; p < SPLITS; p++) {
        const float4 v = *(const float4*)&g_part[(size_t)p * (NODES * NC) + i4];
        s.x += v.x; s.y += v.y; s.z += v.z; s.w += v.w;
    }
    s.x *= CORR; s.y *= CORR; s.z *= CORR; s.w *= CORR;
    *(float4*)&out[i4] = s;
}

// ---------------------------------------------------------------------------
extern "C" void kernel_launch(void* const* d_in, const int* in_sizes, int n_in,
                              void* d_out, int out_size) {
    const float* x   = (const float*)d_in[0];   // (4096, 32, 4)
    const float* adj = (const float*)d_in[1];   // (4096, 4096, 4)
    const float* w   = (const float*)d_in[2];   // (32, 32, 4)
    float* out = (float*)d_out;                 // (4096, 32, 4)
    (void)in_sizes; (void)n_in; (void)out_size;

    cudaFuncSetAttribute(gemm_kernel,
                         cudaFuncAttributeMaxDynamicSharedMemorySize, SMEM_BYTES);

    prep_kernel<<<512, 128>>>(x, w);
    gemm_kernel<<<dim3(NODES / BM, SPLITS), 128, SMEM_BYTES>>>(adj);
    reduce_kernel<<<(NODES * NC) / 1024, 256>>>(out);
}

// round 6
// speedup vs baseline: 5.0903x; 1.5561x over previous
#include <cuda_runtime.h>
#include <cuda_fp16.h>
#include <cstdint>

// ---------------------------------------------------------------------------
// out[n, e*4+a] = sum_{m,b} adj[n, m*4+b] * Vk[m*4+b, e*4+a]
// One GEMM: C[4096,128] = A[4096,16384] @ Vk.  A = adj fp32 (converted to fp16
// in-kernel), B = Vk precomputed as packed fp16.  mma.m16n8k16.f16.f32.
// ---------------------------------------------------------------------------
#define NODES 4096
#define KTOT  16384
#define NC    128

#define BM 128
#define BK 32
#define SPLITS 8
#define KCH   (KTOT / SPLITS)   // 2048
#define ITERS (KCH / BK)        // 64

// B operand, fp16, fragment-packed per 16-k slab:
//   value B[k][col] at g_Vp[slab*2048 + col*16 + c*4 + j]
//   where slab=k>>4, kk=k&15, c=(kk>>1)&3, j=(kk&1)|((kk>>3)<<1)
__device__ __align__(128) __half g_Vp[KTOT * NC];     // 4 MB
__device__ float g_part[SPLITS * NODES * NC];         // 16 MB

// ------------------------------ helpers ------------------------------------
__device__ __forceinline__ uint32_t smem_u32(const void* p) {
    uint32_t a;
    asm("{ .reg .u64 t; cvta.to.shared.u64 t, %1; cvt.u32.u64 %0, t; }"
        : "=r"(a) : "l"(p));
    return a;
}
__device__ __forceinline__ void cp_async16(uint32_t dst, const void* src) {
    asm volatile("cp.async.cg.shared.global [%0], [%1], 16;"
                 :: "r"(dst), "l"(src) : "memory");
}
__device__ __forceinline__ void cp_commit() {
    asm volatile("cp.async.commit_group;" ::: "memory");
}
template <int N>
__device__ __forceinline__ void cp_wait() {
    asm volatile("cp.async.wait_group %0;" :: "n"(N) : "memory");
}
__device__ __forceinline__ void ldmatrix_x4(uint32_t* r, uint32_t addr) {
    asm volatile("ldmatrix.sync.aligned.m8n8.x4.shared.b16 {%0,%1,%2,%3}, [%4];"
                 : "=r"(r[0]), "=r"(r[1]), "=r"(r[2]), "=r"(r[3]) : "r"(addr));
}
__device__ __forceinline__ void mma_f16(float* d, const uint32_t* a,
                                        const uint32_t* b) {
    asm volatile(
        "mma.sync.aligned.m16n8k16.row.col.f32.f16.f16.f32 "
        "{%0,%1,%2,%3}, {%4,%5,%6,%7}, {%8,%9}, {%0,%1,%2,%3};"
        : "+f"(d[0]), "+f"(d[1]), "+f"(d[2]), "+f"(d[3])
        : "r"(a[0]), "r"(a[1]), "r"(a[2]), "r"(a[3]), "r"(b[0]), "r"(b[1]));
}
__device__ __forceinline__ uint32_t cvt_f16x2(float lo, float hi) {
    uint32_t h;
    asm("cvt.rn.f16x2.f32 %0, %1, %2;" : "=r"(h) : "f"(hi), "f"(lo));
    return h;
}

// ---------------------------------------------------------------------------
// prep: one block per 16-k slab (4 nodes).  Writes fragment-packed fp16 g_Vp.
// ---------------------------------------------------------------------------
__global__ __launch_bounds__(128) void prep_kernel(const float* __restrict__ x,
                                                   const float* __restrict__ w) {
    __shared__ float ws[4096];
    __shared__ float xs[512];
    __shared__ __align__(16) __half stage[2048];
    const int t = threadIdx.x;
    const int s = blockIdx.x;                 // slab 0..1023
#pragma unroll
    for (int i = 0; i < 32; i++) ws[i * 128 + t] = w[i * 128 + t];
#pragma unroll
    for (int i = 0; i < 4; i++) xs[i * 128 + t] = x[(size_t)(s * 4 + i) * 128 + t];
    __syncthreads();
    const int a = t & 3, e = t >> 2;
#pragma unroll
    for (int mi = 0; mi < 4; mi++) {
#pragma unroll
        for (int b = 0; b < 4; b++) {
            float acc = 0.f;
#pragma unroll
            for (int d = 0; d < 32; d++)
                acc += xs[mi * 128 + d * 4 + ((a - b) & 3)] *
                       ws[d * 128 + e * 4 + b];
            const int kk = mi * 4 + b;
            const int c = (kk >> 1) & 3;
            const int j = (kk & 1) | ((kk >> 3) << 1);
            stage[t * 16 + c * 4 + j] = __float2half_rn(acc);
        }
    }
    __syncthreads();
    uint4* dst = (uint4*)(g_Vp + (size_t)s * 2048);
    const uint4* src = (const uint4*)stage;
    dst[t] = src[t];
    dst[t + 128] = src[t + 128];
}

// ---------------------------------------------------------------------------
// GEMM: grid (32 m-tiles, 8 splits), 256 thr = 8 warps (4m x 2n),
// warp tile 32x64, mma m16n8k16 f16.f32.  A: LDG f32 -> cvt -> swizzled smem,
// ldmatrix.x4 fragments.  B: flat cp.async of packed fp16, lds.64 fragments.
// ---------------------------------------------------------------------------
__global__ __launch_bounds__(256, 2) void gemm_kernel(const float* __restrict__ A) {
    __shared__ __align__(16) __half Asm[2][128 * 32];   // 16 KB, swizzled
    __shared__ __align__(16) __half Bsm[3][32 * 128];   // 24 KB, packed

    const uint32_t asb = smem_u32(Asm);
    const uint32_t bsb = smem_u32(Bsm);
    const int tid = threadIdx.x;
    const int lane = tid & 31;
    const int wid = tid >> 5;
    const int wm = (wid & 3) * 32;
    const int wn = (wid >> 2) * 64;
    const int g = lane >> 2;
    const int c = lane & 3;

    const int m0 = blockIdx.x * BM;
    const int k0 = blockIdx.y * KCH;
    const __half* Bsrc = g_Vp + (size_t)(k0 >> 4) * 2048;

    // A-fragment ldmatrix addresses (per [mi][ks]), swizzle ch ^= (r&3)
    const int row_l = (lane & 7) | (((lane >> 3) & 1) << 3);
    const int khalf = lane >> 4;
    uint32_t a_addr[2][2];
#pragma unroll
    for (int mi = 0; mi < 2; mi++)
#pragma unroll
        for (int ks = 0; ks < 2; ks++) {
            const int r = wm + mi * 16 + row_l;
            const int ch = (ks * 2 + khalf) ^ (r & 3);
            a_addr[mi][ks] = asb + (uint32_t)(r * 64 + ch * 16);
        }
    const uint32_t b_off = (uint32_t)((wn + g) * 32 + c * 8);

    // A loader mapping: idx = p*256+tid -> row=idx>>3, 8B k-chunk kq=idx&7
    const int a_row = tid >> 3;
    const int a_kq = tid & 7;

    float acc[2][8][4];
#pragma unroll
    for (int mi = 0; mi < 2; mi++)
#pragma unroll
        for (int ni = 0; ni < 8; ni++)
#pragma unroll
            for (int j = 0; j < 4; j++) acc[mi][ni][j] = 0.f;

    float4 pf[4];
    auto ldgA = [&](int it) {
        if (it < ITERS) {
            const int ko = k0 + it * BK;
#pragma unroll
            for (int p = 0; p < 4; p++)
                pf[p] = *(const float4*)(A + (size_t)(m0 + a_row + p * 32) * KTOT +
                                         ko + a_kq * 4);
        }
    };
    auto stsA = [&](int it) {
        if (it < ITERS) {
            const uint32_t base = asb + (uint32_t)(it & 1) * 8192u;
#pragma unroll
            for (int p = 0; p < 4; p++) {
                const int row = a_row + p * 32;
                const uint32_t off =
                    (uint32_t)(row * 64 + (((a_kq >> 1) ^ (row & 3)) * 16) +
                               (a_kq & 1) * 8);
                const uint32_t h0 = cvt_f16x2(pf[p].x, pf[p].y);
                const uint32_t h1 = cvt_f16x2(pf[p].z, pf[p].w);
                asm volatile("st.shared.v2.b32 [%0], {%1, %2};"
                             :: "r"(base + off), "r"(h0), "r"(h1) : "memory");
            }
        }
    };
    auto cpB = [&](int it) {
        if (it < ITERS) {
            const uint32_t bd = bsb + (uint32_t)(it % 3) * 8192u;
            const char* src = (const char*)(Bsrc + it * 4096);
#pragma unroll
            for (int p = 0; p < 2; p++) {
                const int idx = tid + p * 256;
                cp_async16(bd + (uint32_t)idx * 16, src + idx * 16);
            }
        }
    };

    // prologue
    ldgA(0);
    cpB(0); cp_commit();
    cpB(1); cp_commit();
    stsA(0);
    ldgA(1);

    for (int it = 0; it < ITERS; it++) {
        cp_wait<1>();
        __syncthreads();

        cpB(it + 2); cp_commit();
        stsA(it + 1);
        ldgA(it + 2);

        const uint32_t a_st = (uint32_t)(it & 1) * 8192u;
        const uint32_t b_st = bsb + (uint32_t)(it % 3) * 8192u + b_off;
#pragma unroll
        for (int ks = 0; ks < 2; ks++) {
            uint32_t af[2][4];
            ldmatrix_x4(af[0], a_addr[0][ks] + a_st);
            ldmatrix_x4(af[1], a_addr[1][ks] + a_st);
            uint32_t bf[8][2];
#pragma unroll
            for (int ni = 0; ni < 8; ni++)
                asm volatile("ld.shared.v2.b32 {%0, %1}, [%2];"
                             : "=r"(bf[ni][0]), "=r"(bf[ni][1])
                             : "r"(b_st + (uint32_t)(ks * 4096 + ni * 256)));
#pragma unroll
            for (int mi = 0; mi < 2; mi++)
#pragma unroll
                for (int ni = 0; ni < 8; ni++)
                    mma_f16(acc[mi][ni], af[mi], bf[ni]);
        }
    }

    // epilogue -> split-K partials
    float* outp = g_part + (size_t)blockIdx.y * (NODES * NC);
#pragma unroll
    for (int mi = 0; mi < 2; mi++) {
        const int row = m0 + wm + mi * 16 + g;
#pragma unroll
        for (int ni = 0; ni < 8; ni++) {
            const int col = wn + ni * 8 + 2 * c;
            *(float2*)&outp[(size_t)row * NC + col] =
                make_float2(acc[mi][ni][0], acc[mi][ni][1]);
            *(float2*)&outp[(size_t)(row + 8) * NC + col] =
                make_float2(acc[mi][ni][2], acc[mi][ni][3]);
        }
    }
}

// ---------------------------------------------------------------------------
__global__ __launch_bounds__(256) void reduce_kernel(float* __restrict__ out) {
    const int i4 = (blockIdx.x * 256 + threadIdx.x) * 4;
    float4 s = make_float4(0.f, 0.f, 0.f, 0.f);
#pragma unroll
    for (int p = 0; p < SPLITS; p++) {
        const float4 v = *(const float4*)&g_part[(size_t)p * (NODES * NC) + i4];
        s.x += v.x; s.y += v.y; s.z += v.z; s.w += v.w;
    }
    *(float4*)&out[i4] = s;
}

// ---------------------------------------------------------------------------
extern "C" void kernel_launch(void* const* d_in, const int* in_sizes, int n_in,
                              void* d_out, int out_size) {
    const float* x   = (const float*)d_in[0];   // (4096, 32, 4)
    const float* adj = (const float*)d_in[1];   // (4096, 4096, 4)
    const float* w   = (const float*)d_in[2];   // (32, 32, 4)
    float* out = (float*)d_out;                 // (4096, 32, 4)
    (void)in_sizes; (void)n_in; (void)out_size;

    prep_kernel<<<1024, 128>>>(x, w);
    gemm_kernel<<<dim3(NODES / BM, SPLITS), 256>>>(adj);
    reduce_kernel<<<(NODES * NC) / 1024, 256>>>(out);
}

// round 7
// speedup vs baseline: 5.2060x; 1.0227x over previous
#include <cuda_runtime.h>
#include <cuda_fp16.h>
#include <cstdint>

// ---------------------------------------------------------------------------
// out[n, e*4+a] = sum_{m,b} adj[n, m*4+b] * Vk[m*4+b, e*4+a]
// C[4096,128] = A[4096,16384] @ Vk.  A fp32 -> fp16 in-kernel, B packed fp16.
// mma.m16n8k16.f16.f32.  Split-K = 9 (uneven) for 288-CTA wave balance.
// ---------------------------------------------------------------------------
#define NODES 4096
#define KTOT  16384
#define NC    128

#define BM 128
#define BK 32
#define SPLITS 9
#define KB_TOTAL (KTOT / BK)    // 512 k-blocks
#define KB_PER   57             // splits 0..7: 57, split 8: 56

// B operand, fp16, fragment-packed per 16-k slab:
//   value B[k][col] at g_Vp[slab*2048 + col*16 + c*4 + j]
//   slab=k>>4, kk=k&15, c=(kk>>1)&3, j=(kk&1)|((kk>>3)<<1)
__device__ __align__(128) __half g_Vp[KTOT * NC];     // 4 MB
__device__ float g_part[SPLITS * NODES * NC];         // 18 MB

// ------------------------------ helpers ------------------------------------
__device__ __forceinline__ uint32_t smem_u32(const void* p) {
    uint32_t a;
    asm("{ .reg .u64 t; cvta.to.shared.u64 t, %1; cvt.u32.u64 %0, t; }"
        : "=r"(a) : "l"(p));
    return a;
}
__device__ __forceinline__ void cp_async16(uint32_t dst, const void* src) {
    asm volatile("cp.async.cg.shared.global [%0], [%1], 16;"
                 :: "r"(dst), "l"(src) : "memory");
}
__device__ __forceinline__ void cp_commit() {
    asm volatile("cp.async.commit_group;" ::: "memory");
}
template <int N>
__device__ __forceinline__ void cp_wait() {
    asm volatile("cp.async.wait_group %0;" :: "n"(N) : "memory");
}
__device__ __forceinline__ void ldmatrix_x4(uint32_t* r, uint32_t addr) {
    asm volatile("ldmatrix.sync.aligned.m8n8.x4.shared.b16 {%0,%1,%2,%3}, [%4];"
                 : "=r"(r[0]), "=r"(r[1]), "=r"(r[2]), "=r"(r[3]) : "r"(addr));
}
__device__ __forceinline__ void mma_f16(float* d, const uint32_t* a,
                                        const uint32_t* b) {
    asm volatile(
        "mma.sync.aligned.m16n8k16.row.col.f32.f16.f16.f32 "
        "{%0,%1,%2,%3}, {%4,%5,%6,%7}, {%8,%9}, {%0,%1,%2,%3};"
        : "+f"(d[0]), "+f"(d[1]), "+f"(d[2]), "+f"(d[3])
        : "r"(a[0]), "r"(a[1]), "r"(a[2]), "r"(a[3]), "r"(b[0]), "r"(b[1]));
}
__device__ __forceinline__ uint32_t cvt_f16x2(float lo, float hi) {
    uint32_t h;
    asm("cvt.rn.f16x2.f32 %0, %1, %2;" : "=r"(h) : "f"(hi), "f"(lo));
    return h;
}

// ---------------------------------------------------------------------------
// prep: 1024 blocks x 512 thr; block = one 16-k slab (4 nodes); thread =
// (node-in-slab mi, col).  Writes fragment-packed fp16 g_Vp.
// ---------------------------------------------------------------------------
__global__ __launch_bounds__(512) void prep_kernel(const float* __restrict__ x,
                                                   const float* __restrict__ w) {
    __shared__ float ws[4096];
    __shared__ float xs[512];
    __shared__ __align__(16) __half stage[2048];
    const int t = threadIdx.x;
    const int s = blockIdx.x;                 // slab 0..1023
#pragma unroll
    for (int i = 0; i < 8; i++) ws[i * 512 + t] = w[i * 512 + t];
    xs[t] = x[(size_t)s * 512 + t];
    __syncthreads();

    const int mi = t >> 7;                    // node within slab
    const int tc = t & 127;                   // output col
    const int a = tc & 3, e = tc >> 2;
    float acc[4] = {0.f, 0.f, 0.f, 0.f};
#pragma unroll
    for (int d = 0; d < 32; d++)
#pragma unroll
        for (int b = 0; b < 4; b++)
            acc[b] += xs[mi * 128 + d * 4 + ((a - b) & 3)] *
                      ws[d * 128 + e * 4 + b];
#pragma unroll
    for (int b = 0; b < 4; b++) {
        const int kk = mi * 4 + b;
        const int c = (kk >> 1) & 3;
        const int j = (kk & 1) | ((kk >> 3) << 1);
        stage[tc * 16 + c * 4 + j] = __float2half_rn(acc[b]);
    }
    __syncthreads();
    if (t < 256) {
        uint4* dst = (uint4*)(g_Vp + (size_t)s * 2048);
        dst[t] = ((const uint4*)stage)[t];
    }
}

// ---------------------------------------------------------------------------
// GEMM: grid (32 m-tiles, 9 splits), 256 thr = 8 warps (4m x 2n),
// warp tile 32x64, mma m16n8k16 f16.f32.
// ---------------------------------------------------------------------------
__global__ __launch_bounds__(256, 2) void gemm_kernel(const float* __restrict__ A) {
    __shared__ __align__(16) __half Asm[2][128 * 32];   // 16 KB, swizzled
    __shared__ __align__(16) __half Bsm[3][32 * 128];   // 24 KB, packed

    const uint32_t asb = smem_u32(Asm);
    const uint32_t bsb = smem_u32(Bsm);
    const int tid = threadIdx.x;
    const int lane = tid & 31;
    const int wid = tid >> 5;
    const int wm = (wid & 3) * 32;
    const int wn = (wid >> 2) * 64;
    const int g = lane >> 2;
    const int c = lane & 3;

    const int m0 = blockIdx.x * BM;
    const int kb0 = blockIdx.y * KB_PER;
    const int cnt = min(KB_PER, KB_TOTAL - kb0);
    const int k0 = kb0 * BK;
    const __half* Bsrc = g_Vp + (size_t)(k0 >> 4) * 2048;

    // A-fragment ldmatrix addresses (per [mi][ks]), swizzle ch ^= (r&3)
    const int row_l = (lane & 7) | (((lane >> 3) & 1) << 3);
    const int khalf = lane >> 4;
    uint32_t a_addr[2][2];
#pragma unroll
    for (int mi = 0; mi < 2; mi++)
#pragma unroll
        for (int ks = 0; ks < 2; ks++) {
            const int r = wm + mi * 16 + row_l;
            const int ch = (ks * 2 + khalf) ^ (r & 3);
            a_addr[mi][ks] = asb + (uint32_t)(r * 64 + ch * 16);
        }
    const uint32_t b_off = (uint32_t)((wn + g) * 32 + c * 8);

    const int a_row = tid >> 3;
    const int a_kq = tid & 7;

    float acc[2][8][4];
#pragma unroll
    for (int mi = 0; mi < 2; mi++)
#pragma unroll
        for (int ni = 0; ni < 8; ni++)
#pragma unroll
            for (int j = 0; j < 4; j++) acc[mi][ni][j] = 0.f;

    float4 pf[4];
    auto ldgA = [&](int it) {
        if (it < cnt) {
            const int ko = k0 + it * BK;
#pragma unroll
            for (int p = 0; p < 4; p++)
                pf[p] = *(const float4*)(A + (size_t)(m0 + a_row + p * 32) * KTOT +
                                         ko + a_kq * 4);
        }
    };
    auto stsA = [&](int it) {
        if (it < cnt) {
            const uint32_t base = asb + (uint32_t)(it & 1) * 8192u;
#pragma unroll
            for (int p = 0; p < 4; p++) {
                const int row = a_row + p * 32;
                const uint32_t off =
                    (uint32_t)(row * 64 + (((a_kq >> 1) ^ (row & 3)) * 16) +
                               (a_kq & 1) * 8);
                const uint32_t h0 = cvt_f16x2(pf[p].x, pf[p].y);
                const uint32_t h1 = cvt_f16x2(pf[p].z, pf[p].w);
                asm volatile("st.shared.v2.b32 [%0], {%1, %2};"
                             :: "r"(base + off), "r"(h0), "r"(h1) : "memory");
            }
        }
    };
    auto cpB = [&](int it) {
        if (it < cnt) {
            const uint32_t bd = bsb + (uint32_t)(it % 3) * 8192u;
            const char* src = (const char*)(Bsrc + (size_t)it * 4096);
#pragma unroll
            for (int p = 0; p < 2; p++) {
                const int idx = tid + p * 256;
                cp_async16(bd + (uint32_t)idx * 16, src + idx * 16);
            }
        }
    };

    // prologue
    ldgA(0);
    cpB(0); cp_commit();
    cpB(1); cp_commit();
    stsA(0);
    ldgA(1);

    for (int it = 0; it < cnt; it++) {
        cp_wait<1>();
        __syncthreads();

        cpB(it + 2); cp_commit();
        stsA(it + 1);
        ldgA(it + 2);

        const uint32_t a_st = (uint32_t)(it & 1) * 8192u;
        const uint32_t b_st = bsb + (uint32_t)(it % 3) * 8192u + b_off;
#pragma unroll
        for (int ks = 0; ks < 2; ks++) {
            uint32_t af[2][4];
            ldmatrix_x4(af[0], a_addr[0][ks] + a_st);
            ldmatrix_x4(af[1], a_addr[1][ks] + a_st);
            uint32_t bf[8][2];
#pragma unroll
            for (int ni = 0; ni < 8; ni++)
                asm volatile("ld.shared.v2.b32 {%0, %1}, [%2];"
                             : "=r"(bf[ni][0]), "=r"(bf[ni][1])
                             : "r"(b_st + (uint32_t)(ks * 4096 + ni * 256)));
#pragma unroll
            for (int mi = 0; mi < 2; mi++)
#pragma unroll
                for (int ni = 0; ni < 8; ni++)
                    mma_f16(acc[mi][ni], af[mi], bf[ni]);
        }
    }

    // epilogue -> split-K partials
    float* outp = g_part + (size_t)blockIdx.y * (NODES * NC);
#pragma unroll
    for (int mi = 0; mi < 2; mi++) {
        const int row = m0 + wm + mi * 16 + g;
#pragma unroll
        for (int ni = 0; ni < 8; ni++) {
            const int col = wn + ni * 8 + 2 * c;
            *(float2*)&outp[(size_t)row * NC + col] =
                make_float2(acc[mi][ni][0], acc[mi][ni][1]);
            *(float2*)&outp[(size_t)(row + 8) * NC + col] =
                make_float2(acc[mi][ni][2], acc[mi][ni][3]);
        }
    }
}

// ---------------------------------------------------------------------------
__global__ __launch_bounds__(256) void reduce_kernel(float* __restrict__ out) {
    const int i4 = (blockIdx.x * 256 + threadIdx.x) * 4;
    float4 s = make_float4(0.f, 0.f, 0.f, 0.f);
#pragma unroll
    for (int p = 0; p < SPLITS; p++) {
        const float4 v = *(const float4*)&g_part[(size_t)p * (NODES * NC) + i4];
        s.x += v.x; s.y += v.y; s.z += v.z; s.w += v.w;
    }
    *(float4*)&out[i4] = s;
}

// ---------------------------------------------------------------------------
extern "C" void kernel_launch(void* const* d_in, const int* in_sizes, int n_in,
                              void* d_out, int out_size) {
    const float* x   = (const float*)d_in[0];   // (4096, 32, 4)
    const float* adj = (const float*)d_in[1];   // (4096, 4096, 4)
    const float* w   = (const float*)d_in[2];   // (32, 32, 4)
    float* out = (float*)d_out;                 // (4096, 32, 4)
    (void)in_sizes; (void)n_in; (void)out_size;

    prep_kernel<<<1024, 512>>>(x, w);
    gemm_kernel<<<dim3(NODES / BM, SPLITS), 256>>>(adj);
    reduce_kernel<<<(NODES * NC) / 1024, 256>>>(out);
}

// round 9
// speedup vs baseline: 5.5807x; 1.0720x over previous
#include <cuda_runtime.h>
#include <cuda_fp16.h>
#include <cstdint>

// ---------------------------------------------------------------------------
// out[n, e*4+a] = sum_{m,b} adj[n, m*4+b] * Vk[m*4+b, e*4+a]
// C[4096,128] = A[4096,16384] @ Vk.  A fp32 -> fp16 in-kernel, B packed fp16.
// mma.m16n8k16.f16.f32.  Split-K = 9 (uneven) for 288-CTA wave balance.
// ---------------------------------------------------------------------------
#define NODES 4096
#define KTOT  16384
#define NC    128

#define BM 128
#define BK 32
#define SPLITS 9
#define KB_TOTAL (KTOT / BK)    // 512 k-blocks
#define KB_PER   57             // splits 0..7: 57, split 8: 56

// B operand, fp16, fragment-packed per 16-k slab:
//   value B[k][col] at g_Vp[slab*2048 + col*16 + c*4 + j]
//   slab=k>>4, kk=k&15, c=(kk>>1)&3, j=(kk&1)|((kk>>3)<<1)
__device__ __align__(128) __half g_Vp[KTOT * NC];     // 4 MB
__device__ float g_part[SPLITS * NODES * NC];         // 18 MB

// ------------------------------ helpers ------------------------------------
__device__ __forceinline__ uint32_t smem_u32(const void* p) {
    uint32_t a;
    asm("{ .reg .u64 t; cvta.to.shared.u64 t, %1; cvt.u32.u64 %0, t; }"
        : "=r"(a) : "l"(p));
    return a;
}
__device__ __forceinline__ void cp_async16(uint32_t dst, const void* src) {
    asm volatile("cp.async.cg.shared.global [%0], [%1], 16;"
                 :: "r"(dst), "l"(src) : "memory");
}
__device__ __forceinline__ void cp_commit() {
    asm volatile("cp.async.commit_group;" ::: "memory");
}
template <int N>
__device__ __forceinline__ void cp_wait() {
    asm volatile("cp.async.wait_group %0;" :: "n"(N) : "memory");
}
__device__ __forceinline__ void ldmatrix_x4(uint32_t* r, uint32_t addr) {
    asm volatile("ldmatrix.sync.aligned.m8n8.x4.shared.b16 {%0,%1,%2,%3}, [%4];"
                 : "=r"(r[0]), "=r"(r[1]), "=r"(r[2]), "=r"(r[3]) : "r"(addr));
}
__device__ __forceinline__ void mma_f16(float* d, const uint32_t* a,
                                        const uint32_t* b) {
    asm volatile(
        "mma.sync.aligned.m16n8k16.row.col.f32.f16.f16.f32 "
        "{%0,%1,%2,%3}, {%4,%5,%6,%7}, {%8,%9}, {%0,%1,%2,%3};"
        : "+f"(d[0]), "+f"(d[1]), "+f"(d[2]), "+f"(d[3])
        : "r"(a[0]), "r"(a[1]), "r"(a[2]), "r"(a[3]), "r"(b[0]), "r"(b[1]));
}
__device__ __forceinline__ uint32_t cvt_f16x2(float lo, float hi) {
    uint32_t h;
    asm("cvt.rn.f16x2.f32 %0, %1, %2;" : "=r"(h) : "f"(hi), "f"(lo));
    return h;
}

// ---------------------------------------------------------------------------
// prep: 128 blocks x 256 thr; block = 32 nodes (8 slabs).  W cached in regs,
// pre-rotated by a and f32x2-packed; x via broadcast LDS; f32x2 FMA core.
// Identity: acc[b] += x[(a-b)&3] w[b]  ==>  acc_rot[j] += x[j] w_rot[j],
//   w_rot[j] = w[(a-j)&3], acc[b] = acc_rot[(a-b)&3].
// ---------------------------------------------------------------------------
__global__ __launch_bounds__(256) void prep_kernel(const float* __restrict__ x,
                                                   const float* __restrict__ w) {
    extern __shared__ float dynsmem[];
    float* xs = dynsmem;                            // 32 nodes x 128 = 16 KB
    __half* stage = (__half*)(dynsmem + 4096);      // 8 slabs x 2048 = 32 KB

    const int t = threadIdx.x;
    const int tc = t & 127;
    const int nh = t >> 7;
    const int a = tc & 3, e = tc >> 2;

    // stage x for 32 nodes (coalesced float4): 4096 floats = 1024 float4
    const float4* xsrc = (const float4*)(x + (size_t)blockIdx.x * 4096);
#pragma unroll
    for (int i = 0; i < 4; i++) ((float4*)xs)[t + i * 256] = xsrc[t + i * 256];

    // W register cache: pre-rotated, packed as f32x2 pairs (j=0,1 | j=2,3)
    unsigned long long wrot2[32][2];
#pragma unroll
    for (int d = 0; d < 32; d++) {
        float wv0 = __ldg(w + d * 128 + e * 4 + (a & 3));
        float wv1 = __ldg(w + d * 128 + e * 4 + ((a - 1) & 3));
        float wv2 = __ldg(w + d * 128 + e * 4 + ((a - 2) & 3));
        float wv3 = __ldg(w + d * 128 + e * 4 + ((a - 3) & 3));
        asm("mov.b64 %0, {%1, %2};" : "=l"(wrot2[d][0]) : "f"(wv0), "f"(wv1));
        asm("mov.b64 %0, {%1, %2};" : "=l"(wrot2[d][1]) : "f"(wv2), "f"(wv3));
    }
    __syncthreads();

#pragma unroll 1
    for (int i = 0; i < 16; i++) {
        const int ml = nh * 16 + i;
        const unsigned long long* xp =
            (const unsigned long long*)(xs + ml * 128);
        unsigned long long acc2[2] = {0ULL, 0ULL};  // {0.f,0.f} packed
#pragma unroll
        for (int d = 0; d < 32; d++) {
            const unsigned long long xv0 = xp[d * 2];
            const unsigned long long xv1 = xp[d * 2 + 1];
            asm("fma.rn.f32x2 %0, %1, %2, %0;"
                : "+l"(acc2[0]) : "l"(xv0), "l"(wrot2[d][0]));
            asm("fma.rn.f32x2 %0, %1, %2, %0;"
                : "+l"(acc2[1]) : "l"(xv1), "l"(wrot2[d][1]));
        }
        float ar[4];
        asm("mov.b64 {%0, %1}, %2;" : "=f"(ar[0]), "=f"(ar[1]) : "l"(acc2[0]));
        asm("mov.b64 {%0, %1}, %2;" : "=f"(ar[2]), "=f"(ar[3]) : "l"(acc2[1]));

        const int mi = ml & 3;
        __half* sb = stage + (ml >> 2) * 2048 + tc * 16;
#pragma unroll
        for (int jp = 0; jp < 4; jp++) {
            const int b = (a - jp) & 3;
            const int kk = mi * 4 + b;
            const int cc = (kk >> 1) & 3;
            const int jj = (kk & 1) | ((kk >> 3) << 1);
            sb[cc * 4 + jj] = __float2half_rn(ar[jp]);
        }
    }
    __syncthreads();

    // coalesced copy-out: 8 slabs x 2048 halfs = 32768 B = 2048 uint4
    uint4* dst = (uint4*)(g_Vp + (size_t)blockIdx.x * (8 * 2048));
    const uint4* srcs = (const uint4*)stage;
#pragma unroll
    for (int i = 0; i < 8; i++) dst[t + i * 256] = srcs[t + i * 256];
}

// ---------------------------------------------------------------------------
// GEMM: grid (32 m-tiles, 9 splits), 256 thr = 8 warps (4m x 2n),
// warp tile 32x64, mma m16n8k16 f16.f32.  (unchanged, validated R7)
// ---------------------------------------------------------------------------
__global__ __launch_bounds__(256, 2) void gemm_kernel(const float* __restrict__ A) {
    __shared__ __align__(16) __half Asm[2][128 * 32];   // 16 KB, swizzled
    __shared__ __align__(16) __half Bsm[3][32 * 128];   // 24 KB, packed

    const uint32_t asb = smem_u32(Asm);
    const uint32_t bsb = smem_u32(Bsm);
    const int tid = threadIdx.x;
    const int lane = tid & 31;
    const int wid = tid >> 5;
    const int wm = (wid & 3) * 32;
    const int wn = (wid >> 2) * 64;
    const int g = lane >> 2;
    const int c = lane & 3;

    const int m0 = blockIdx.x * BM;
    const int kb0 = blockIdx.y * KB_PER;
    const int cnt = min(KB_PER, KB_TOTAL - kb0);
    const int k0 = kb0 * BK;
    const __half* Bsrc = g_Vp + (size_t)(k0 >> 4) * 2048;

    const int row_l = (lane & 7) | (((lane >> 3) & 1) << 3);
    const int khalf = lane >> 4;
    uint32_t a_addr[2][2];
#pragma unroll
    for (int mi = 0; mi < 2; mi++)
#pragma unroll
        for (int ks = 0; ks < 2; ks++) {
            const int r = wm + mi * 16 + row_l;
            const int ch = (ks * 2 + khalf) ^ (r & 3);
            a_addr[mi][ks] = asb + (uint32_t)(r * 64 + ch * 16);
        }
    const uint32_t b_off = (uint32_t)((wn + g) * 32 + c * 8);

    const int a_row = tid >> 3;
    const int a_kq = tid & 7;

    float acc[2][8][4];
#pragma unroll
    for (int mi = 0; mi < 2; mi++)
#pragma unroll
        for (int ni = 0; ni < 8; ni++)
#pragma unroll
            for (int j = 0; j < 4; j++) acc[mi][ni][j] = 0.f;

    float4 pf[4];
    auto ldgA = [&](int it) {
        if (it < cnt) {
            const int ko = k0 + it * BK;
#pragma unroll
            for (int p = 0; p < 4; p++)
                pf[p] = *(const float4*)(A + (size_t)(m0 + a_row + p * 32) * KTOT +
                                         ko + a_kq * 4);
        }
    };
    auto stsA = [&](int it) {
        if (it < cnt) {
            const uint32_t base = asb + (uint32_t)(it & 1) * 8192u;
#pragma unroll
            for (int p = 0; p < 4; p++) {
                const int row = a_row + p * 32;
                const uint32_t off =
                    (uint32_t)(row * 64 + (((a_kq >> 1) ^ (row & 3)) * 16) +
                               (a_kq & 1) * 8);
                const uint32_t h0 = cvt_f16x2(pf[p].x, pf[p].y);
                const uint32_t h1 = cvt_f16x2(pf[p].z, pf[p].w);
                asm volatile("st.shared.v2.b32 [%0], {%1, %2};"
                             :: "r"(base + off), "r"(h0), "r"(h1) : "memory");
            }
        }
    };
    auto cpB = [&](int it) {
        if (it < cnt) {
            const uint32_t bd = bsb + (uint32_t)(it % 3) * 8192u;
            const char* src = (const char*)(Bsrc + (size_t)it * 4096);
#pragma unroll
            for (int p = 0; p < 2; p++) {
                const int idx = tid + p * 256;
                cp_async16(bd + (uint32_t)idx * 16, src + idx * 16);
            }
        }
    };

    // prologue
    ldgA(0);
    cpB(0); cp_commit();
    cpB(1); cp_commit();
    stsA(0);
    ldgA(1);

    for (int it = 0; it < cnt; it++) {
        cp_wait<1>();
        __syncthreads();

        cpB(it + 2); cp_commit();
        stsA(it + 1);
        ldgA(it + 2);

        const uint32_t a_st = (uint32_t)(it & 1) * 8192u;
        const uint32_t b_st = bsb + (uint32_t)(it % 3) * 8192u + b_off;
#pragma unroll
        for (int ks = 0; ks < 2; ks++) {
            uint32_t af[2][4];
            ldmatrix_x4(af[0], a_addr[0][ks] + a_st);
            ldmatrix_x4(af[1], a_addr[1][ks] + a_st);
            uint32_t bf[8][2];
#pragma unroll
            for (int ni = 0; ni < 8; ni++)
                asm volatile("ld.shared.v2.b32 {%0, %1}, [%2];"
                             : "=r"(bf[ni][0]), "=r"(bf[ni][1])
                             : "r"(b_st + (uint32_t)(ks * 4096 + ni * 256)));
#pragma unroll
            for (int mi = 0; mi < 2; mi++)
#pragma unroll
                for (int ni = 0; ni < 8; ni++)
                    mma_f16(acc[mi][ni], af[mi], bf[ni]);
        }
    }

    // epilogue -> split-K partials
    float* outp = g_part + (size_t)blockIdx.y * (NODES * NC);
#pragma unroll
    for (int mi = 0; mi < 2; mi++) {
        const int row = m0 + wm + mi * 16 + g;
#pragma unroll
        for (int ni = 0; ni < 8; ni++) {
            const int col = wn + ni * 8 + 2 * c;
            *(float2*)&outp[(size_t)row * NC + col] =
                make_float2(acc[mi][ni][0], acc[mi][ni][1]);
            *(float2*)&outp[(size_t)(row + 8) * NC + col] =
                make_float2(acc[mi][ni][2], acc[mi][ni][3]);
        }
    }
}

// ---------------------------------------------------------------------------
__global__ __launch_bounds__(256) void reduce_kernel(float* __restrict__ out) {
    const int i4 = (blockIdx.x * 256 + threadIdx.x) * 4;
    float4 s = make_float4(0.f, 0.f, 0.f, 0.f);
#pragma unroll
    for (int p = 0; p < SPLITS; p++) {
        const float4 v = *(const float4*)&g_part[(size_t)p * (NODES * NC) + i4];
        s.x += v.x; s.y += v.y; s.z += v.z; s.w += v.w;
    }
    *(float4*)&out[i4] = s;
}

// ---------------------------------------------------------------------------
extern "C" void kernel_launch(void* const* d_in, const int* in_sizes, int n_in,
                              void* d_out, int out_size) {
    const float* x   = (const float*)d_in[0];   // (4096, 32, 4)
    const float* adj = (const float*)d_in[1];   // (4096, 4096, 4)
    const float* w   = (const float*)d_in[2];   // (32, 32, 4)
    float* out = (float*)d_out;                 // (4096, 32, 4)
    (void)in_sizes; (void)n_in; (void)out_size;

    const int prep_smem = 4096 * 4 + 16384 * 2;   // 48 KB
    cudaFuncSetAttribute(prep_kernel,
                         cudaFuncAttributeMaxDynamicSharedMemorySize, prep_smem);

    prep_kernel<<<128, 256, prep_smem>>>(x, w);
    gemm_kernel<<<dim3(NODES / BM, SPLITS), 256>>>(adj);
    reduce_kernel<<<(NODES * NC) / 1024, 256>>>(out);
}